// round 9
// baseline (speedup 1.0000x reference)
#include <cuda_runtime.h>
#include <cuda_bf16.h>

// Furthest-point sampling — round 9: OUTPUT AS FLOAT32.
// Eight rounds returned rel_err = 1.000000e+00 bit-identically across three
// sync mechanisms, two FP modes, and an in-band diagnostic that should have
// produced 0.66 / 0.82 / 6e3 signatures. The only single cause consistent
// with all of it: the validator reads d_out as float32, so int32 index bit
// patterns look like denormals (~0) and ||out|| ~= 0 -> rel_err == 1.0 exactly.
// This build keeps the proven mechanism chain (pack kernel + ONE 1024-thread
// block, __syncthreads only, plain default-stream launches, 2 graph nodes)
// and changes exactly one thing: indices are stored as (float)idx.
//
// Math (reference-matching):
//   dists: __fadd_rn/__fmul_rn, left-to-right ((dx^2+dy^2)+dz^2), fminf.
//   argmax key: (float_bits(dist)<<32) | (0xFFFFFFFF - idx); dist >= 0 keeps
//   float bits order-preserving; complemented idx makes 64-bit max() prefer
//   the SMALLEST index on exact ties = jnp.argmax first-occurrence. The
//   thread-local scan ascends in index with strict '>', keeping the first max.

#define N_MAX 400000
#define NTHR  1024

__device__ float g_x[N_MAX];
__device__ float g_y[N_MAX];
__device__ float g_z[N_MAX];
__device__ float g_d[N_MAX];

__global__ void fps_pack_kernel(const float* __restrict__ feats, int n) {
    int g = blockIdx.x * blockDim.x + threadIdx.x;
    if (g < n) {
        // feats row stride = 64 floats (256B) -> aligned LDG.128 of first 16B
        float4 v = *reinterpret_cast<const float4*>(feats + (size_t)g * 64);
        g_x[g] = v.x; g_y[g] = v.y; g_z[g] = v.z; g_d[g] = 1e10f;
    }
}

__global__ __launch_bounds__(NTHR, 1)
void fps_main_kernel(const float* __restrict__ feats, int n, int m,
                     float* __restrict__ out)
{
    const int tid  = threadIdx.x;
    const int lane = tid & 31;
    const int warp = tid >> 5;                 // 32 warps
    const int nq   = n >> 2;                   // 400000/4 = 100000 quads

    __shared__ unsigned long long s_red[NTHR / 32];
    __shared__ float s_q[3];
    __shared__ unsigned int s_widx;

    float qx = feats[0], qy = feats[1], qz = feats[2];   // seed = index 0
    if (tid == 0) out[0] = 0.0f;

    for (int i = 0; i < m - 1; ++i) {
        // ---- 1) stream all points: min-dist update + thread-local argmax ----
        float bestd = -1.0f;
        int   besti = 0;
        for (int q = tid; q < nq; q += NTHR) {
            const int g4 = q << 2;
            float4 X = *reinterpret_cast<const float4*>(&g_x[g4]);
            float4 Y = *reinterpret_cast<const float4*>(&g_y[g4]);
            float4 Z = *reinterpret_cast<const float4*>(&g_z[g4]);
            float4 D = *reinterpret_cast<float4*>(&g_d[g4]);

#define FPS_UPD(C, J)                                                       \
            {                                                               \
                float dx = __fadd_rn(X.C, -qx);                             \
                float dy = __fadd_rn(Y.C, -qy);                             \
                float dz = __fadd_rn(Z.C, -qz);                             \
                float dd = __fadd_rn(__fadd_rn(__fmul_rn(dx, dx),           \
                                               __fmul_rn(dy, dy)),         \
                                     __fmul_rn(dz, dz));                    \
                float nd = fminf(D.C, dd);                                  \
                D.C = nd;                                                   \
                if (nd > bestd) { bestd = nd; besti = g4 + (J); }           \
            }
            FPS_UPD(x, 0)
            FPS_UPD(y, 1)
            FPS_UPD(z, 2)
            FPS_UPD(w, 3)
#undef FPS_UPD
            *reinterpret_cast<float4*>(&g_d[g4]) = D;
        }

        // ---- 2) block argmax: warp shfl, then 32 partials in warp 0 ----
        unsigned long long best =
            ((unsigned long long)__float_as_uint(bestd) << 32) |
            (unsigned long long)(0xFFFFFFFFu - (unsigned)besti);
#pragma unroll
        for (int off = 16; off > 0; off >>= 1) {
            unsigned long long o = __shfl_down_sync(0xFFFFFFFFu, best, off);
            best = (o > best) ? o : best;
        }
        if (lane == 0) s_red[warp] = best;
        __syncthreads();                       // sync A
        if (warp == 0) {
            best = s_red[lane];                // exactly 32 warps
#pragma unroll
            for (int off = 16; off > 0; off >>= 1) {
                unsigned long long o = __shfl_down_sync(0xFFFFFFFFu, best, off);
                best = (o > best) ? o : best;
            }
            if (lane == 0) {
                unsigned int widx =
                    0xFFFFFFFFu - (unsigned int)(best & 0xFFFFFFFFull);
                float4 qv = *reinterpret_cast<const float4*>(
                                feats + (size_t)widx * 64);   // immutable
                s_q[0] = qv.x; s_q[1] = qv.y; s_q[2] = qv.z;
                s_widx = widx;
            }
        }
        __syncthreads();                       // sync B

        // ---- 3) broadcast winner; store index AS FLOAT ----
        qx = s_q[0]; qy = s_q[1]; qz = s_q[2];
        if (tid == 0) out[i + 1] = (float)s_widx;
        // WAR safety: next writes to s_red/s_q occur only after all threads
        // (including these readers) pass the next sync A / sync B.
    }
}

extern "C" void kernel_launch(void* const* d_in, const int* in_sizes, int n_in,
                              void* d_out, int out_size) {
    const float* feats = (const float*)d_in[0];
    float* out = (float*)d_out;
    const int n = in_sizes[0] / 64;   // WIDTH = 64 -> N = 400000
    const int m = out_size;           // 1000 indices (stored as float32)

    fps_pack_kernel<<<(n + 255) / 256, 256>>>(feats, n);
    fps_main_kernel<<<1, NTHR>>>(feats, n, m, out);
}

// round 10
// speedup vs baseline: 9.8666x; 9.8666x over previous
#include <cuda_runtime.h>
#include <cuda_bf16.h>
#include <cooperative_groups.h>

namespace cg = cooperative_groups;

// Furthest-point sampling — round 10: the round-4 cooperative persistent
// kernel with the ROOT-CAUSE FIX (output stored as float32 — the validator
// reads d_out as f32; int32 bit patterns denormalize to ~0, which is what
// produced rel_err == 1.0 in every pre-round-9 build).
//
// 148 blocks x 1024 threads, co-residency guaranteed by the cooperative
// launch. Each thread holds 3 points (x,y,z + running min sq-dist) in
// registers -> zero bulk memory traffic per iteration. Per iteration:
//   register dist update -> warp shfl argmax -> smem block argmax ->
//   __stcg per-block packed key (parity double-buffered) -> grid.sync() ->
//   every block redundantly reduces the 148 partials (__ldcg, L1-bypassing)
//   -> winner coords from immutable feats -> smem broadcast.
//
// g_part double-buffered by iteration parity: buffer p's reads (iter i,
// before sync_{i+1}) strictly precede its next writes (iter i+2, after
// sync_{i+1}).
//
// Math (validated EXACT in round 9, rel_err = 0.0):
//   dists: __fadd_rn/__fmul_rn, left-to-right ((dx^2+dy^2)+dz^2), fminf.
//   key: (float_bits(dist)<<32) | (0xFFFFFFFF - idx); dist >= 0 keeps float
//   bits order-preserving; complemented idx => max() prefers the SMALLEST
//   index on exact ties = jnp.argmax first-occurrence.

#define NBLK 148
#define NTHR 1024
#define PPT  3   // ceil(400000 / (148*1024)) = 3 points per thread

__device__ unsigned long long g_part[2][NBLK];

__global__ __launch_bounds__(NTHR, 1)
void fps_coop_kernel(const float* __restrict__ feats, int n, int m,
                     float* __restrict__ out)
{
    cg::grid_group grid = cg::this_grid();

    const int tid  = threadIdx.x;
    const int bid  = blockIdx.x;
    const int gtid = bid * NTHR + tid;
    const int lane = tid & 31;
    const int warp = tid >> 5;
    const int stride = NBLK * NTHR;

    // Register-resident point state
    float px[PPT], py[PPT], pz[PPT], dist[PPT];
#pragma unroll
    for (int k = 0; k < PPT; ++k) {
        int g = gtid + k * stride;
        if (g < n) {
            // feats row = 64 floats (256B); first 16B aligned -> one LDG.128
            float4 v = *reinterpret_cast<const float4*>(feats + (size_t)g * 64);
            px[k] = v.x; py[k] = v.y; pz[k] = v.z;
            dist[k] = 1e10f;
        } else {
            px[k] = 0.f; py[k] = 0.f; pz[k] = 0.f;
            dist[k] = 1e10f;   // excluded from keys below
        }
    }

    // Seed: index 0
    float qx = feats[0], qy = feats[1], qz = feats[2];
    if (gtid == 0) out[0] = 0.0f;

    __shared__ unsigned long long s_red[NTHR / 32];
    __shared__ float s_q[3];
    __shared__ unsigned int s_widx;

    for (int i = 0; i < m - 1; ++i) {
        // ---- 1) min-dist update + local best key ----
        unsigned long long best = 0ull;
#pragma unroll
        for (int k = 0; k < PPT; ++k) {
            int g = gtid + k * stride;
            float dx = __fadd_rn(px[k], -qx);
            float dy = __fadd_rn(py[k], -qy);
            float dz = __fadd_rn(pz[k], -qz);
            float d  = __fadd_rn(__fadd_rn(__fmul_rn(dx, dx),
                                           __fmul_rn(dy, dy)),
                                 __fmul_rn(dz, dz));
            float nd = fminf(dist[k], d);
            dist[k] = nd;
            if (g < n) {
                unsigned long long pk =
                    ((unsigned long long)__float_as_uint(nd) << 32) |
                    (unsigned long long)(0xFFFFFFFFu - (unsigned)g);
                best = (pk > best) ? pk : best;
            }
        }

        // ---- 2) warp + block argmax ----
#pragma unroll
        for (int off = 16; off > 0; off >>= 1) {
            unsigned long long o = __shfl_down_sync(0xFFFFFFFFu, best, off);
            best = (o > best) ? o : best;
        }
        if (lane == 0) s_red[warp] = best;
        __syncthreads();
        if (warp == 0) {
            best = s_red[lane];   // exactly 32 warps
#pragma unroll
            for (int off = 16; off > 0; off >>= 1) {
                unsigned long long o = __shfl_down_sync(0xFFFFFFFFu, best, off);
                best = (o > best) ? o : best;
            }
            if (lane == 0)
                __stcg(&g_part[i & 1][bid], best);   // L2-visible partial
        }

        // ---- 3) grid-wide barrier (release/acquire, gpu scope) ----
        grid.sync();

        // ---- 4) every block redundantly picks the winner ----
        if (warp == 0) {
            unsigned long long b2 = 0ull;
            for (int j = lane; j < NBLK; j += 32) {
                unsigned long long v = __ldcg(&g_part[i & 1][j]);  // bypass L1
                b2 = (v > b2) ? v : b2;
            }
#pragma unroll
            for (int off = 16; off > 0; off >>= 1) {
                unsigned long long o = __shfl_down_sync(0xFFFFFFFFu, b2, off);
                b2 = (o > b2) ? o : b2;
            }
            unsigned int widx = 0xFFFFFFFFu - (unsigned int)(b2 & 0xFFFFFFFFull);
            widx = __shfl_sync(0xFFFFFFFFu, widx, 0);
            if (lane == 0) {
                float4 q = *reinterpret_cast<const float4*>(
                               feats + (size_t)widx * 64);   // immutable input
                s_q[0] = q.x; s_q[1] = q.y; s_q[2] = q.z;
                s_widx = widx;
            }
        }
        __syncthreads();

        // ---- 5) broadcast winner; store index AS FLOAT ----
        qx = s_q[0]; qy = s_q[1]; qz = s_q[2];
        if (bid == 0 && tid == 0) out[i + 1] = (float)s_widx;
        // s_q next overwritten only after the next grid.sync -> safe.
    }
}

extern "C" void kernel_launch(void* const* d_in, const int* in_sizes, int n_in,
                              void* d_out, int out_size) {
    const float* feats = (const float*)d_in[0];
    float* out = (float*)d_out;
    int n = in_sizes[0] / 64;   // WIDTH = 64 -> N = 400000
    int m = out_size;           // 1000

    void* args[4] = { (void*)&feats, (void*)&n, (void*)&m, (void*)&out };
    cudaLaunchCooperativeKernel((void*)fps_coop_kernel,
                                dim3(NBLK), dim3(NTHR), args, 0, (cudaStream_t)0);
}

// round 12
// speedup vs baseline: 13.6646x; 1.3849x over previous
#include <cuda_runtime.h>
#include <cuda_bf16.h>

// Furthest-point sampling — round 12: round-10's passing kernel (5384us,
// issue=8.5% -> all cost in cg::grid_group::sync, which nanosleep-backoff
// spins) with the CG barrier swapped for the round-2-proven counter barrier:
//   lane0: __stcg partial -> __threadfence (release) -> atomicAdd(g_cnt) ->
//   warp0 volatile-spins until g_cnt >= 148*(i+1) (monotone counter, no
//   resets, no per-iteration slots, no designated finisher — the round-11
//   constructs that produced an unexplained IMA are all removed) ->
//   __threadfence (acquire) -> warp0 redundantly reduces the 148 partials.
//
// Everything else is identical to round 10 (passed, rel_err = 0.0):
//   register-resident points (3/thread), parity double-buffered g_part,
//   winner coords from packed L2-hot g_xyz, OUTPUT STORED AS FLOAT32.
//
// Math (validated EXACT): __fadd_rn/__fmul_rn, left-to-right
// ((dx^2+dy^2)+dz^2), fminf; key = (float_bits(dist)<<32) |
// (0xFFFFFFFF - idx) -> 64-bit max prefers smallest index on ties
// (jnp.argmax first-occurrence).

#define N_MAX 400000
#define NBLK  148
#define NTHR  1024
#define PPT   3      // ceil(400000 / (148*1024)) = 3 points per thread

__device__ float4 g_xyz[N_MAX];                  // packed coords (L2-hot)
__device__ unsigned long long g_part[2][NBLK];
__device__ unsigned int g_cnt;

__global__ void fps_init_kernel() {
    if (threadIdx.x == 0) g_cnt = 0u;
}

__global__ void fps_pack_kernel(const float* __restrict__ feats, int n) {
    int g = blockIdx.x * blockDim.x + threadIdx.x;
    if (g < n) {
        float4 v = *reinterpret_cast<const float4*>(feats + (size_t)g * 64);
        g_xyz[g] = make_float4(v.x, v.y, v.z, 0.0f);
    }
}

__global__ __launch_bounds__(NTHR, 1)
void fps_coop_kernel(const float* __restrict__ feats, int n, int m,
                     float* __restrict__ out)
{
    const int tid  = threadIdx.x;
    const int bid  = blockIdx.x;
    const int gtid = bid * NTHR + tid;
    const int lane = tid & 31;
    const int warp = tid >> 5;
    const int stride = NBLK * NTHR;

    // Register-resident point state
    float px[PPT], py[PPT], pz[PPT], dist[PPT];
#pragma unroll
    for (int k = 0; k < PPT; ++k) {
        int g = gtid + k * stride;
        if (g < n) {
            // feats row = 64 floats (256B); first 16B aligned -> one LDG.128
            float4 v = *reinterpret_cast<const float4*>(feats + (size_t)g * 64);
            px[k] = v.x; py[k] = v.y; pz[k] = v.z;
        } else {
            px[k] = 0.f; py[k] = 0.f; pz[k] = 0.f;
        }
        dist[k] = 1e10f;
    }

    float qx = feats[0], qy = feats[1], qz = feats[2];   // seed = index 0
    if (gtid == 0) out[0] = 0.0f;

    __shared__ unsigned long long s_red[NTHR / 32];
    __shared__ float s_q[3];
    __shared__ unsigned int s_widx;

    for (int i = 0; i < m - 1; ++i) {
        // ---- 1) min-dist update + thread-local best key ----
        unsigned long long best = 0ull;
#pragma unroll
        for (int k = 0; k < PPT; ++k) {
            int g = gtid + k * stride;
            float dx = __fadd_rn(px[k], -qx);
            float dy = __fadd_rn(py[k], -qy);
            float dz = __fadd_rn(pz[k], -qz);
            float d  = __fadd_rn(__fadd_rn(__fmul_rn(dx, dx),
                                           __fmul_rn(dy, dy)),
                                 __fmul_rn(dz, dz));
            float nd = fminf(dist[k], d);
            dist[k] = nd;
            if (g < n) {
                unsigned long long pk =
                    ((unsigned long long)__float_as_uint(nd) << 32) |
                    (unsigned long long)(0xFFFFFFFFu - (unsigned)g);
                best = (pk > best) ? pk : best;
            }
        }

        // ---- 2) warp + block argmax ----
#pragma unroll
        for (int off = 16; off > 0; off >>= 1) {
            unsigned long long o = __shfl_down_sync(0xFFFFFFFFu, best, off);
            best = (o > best) ? o : best;
        }
        if (lane == 0) s_red[warp] = best;
        __syncthreads();

        if (warp == 0) {
            best = s_red[lane];                  // exactly 32 warps
#pragma unroll
            for (int off = 16; off > 0; off >>= 1) {
                unsigned long long o = __shfl_down_sync(0xFFFFFFFFu, best, off);
                best = (o > best) ? o : best;
            }

            // ---- 3) publish partial + arrive (round-2-proven barrier) ----
            if (lane == 0) {
                __stcg(&g_part[i & 1][bid], best);
                __threadfence();                 // release partial
                atomicAdd(&g_cnt, 1u);           // arrive
            }
            // all 32 lanes spin on the monotone counter (broadcast load)
            const unsigned int target = (unsigned)(i + 1) * (unsigned)NBLK;
            while (*((volatile unsigned int*)&g_cnt) < target) { }
            __threadfence();                     // acquire partials

            // ---- 4) redundant per-block winner reduce ----
            unsigned long long b2 = 0ull;
            for (int j = lane; j < NBLK; j += 32) {
                unsigned long long v = __ldcg(&g_part[i & 1][j]);
                b2 = (v > b2) ? v : b2;
            }
#pragma unroll
            for (int off = 16; off > 0; off >>= 1) {
                unsigned long long o = __shfl_down_sync(0xFFFFFFFFu, b2, off);
                b2 = (o > b2) ? o : b2;
            }
            if (lane == 0) {
                unsigned int widx =
                    0xFFFFFFFFu - (unsigned int)(b2 & 0xFFFFFFFFull);
                float4 q = g_xyz[widx];          // L2-hot packed coords
                s_q[0] = q.x; s_q[1] = q.y; s_q[2] = q.z;
                s_widx = widx;
            }
        }
        __syncthreads();

        // ---- 5) broadcast winner; store index AS FLOAT ----
        qx = s_q[0]; qy = s_q[1]; qz = s_q[2];
        if (bid == 0 && tid == 0) out[i + 1] = (float)s_widx;
        // WAR safety: s_red/s_q rewritten only after all threads pass this
        // iteration's two __syncthreads. g_part parity gives the double
        // buffer one full barrier of separation between read and rewrite.
    }
}

extern "C" void kernel_launch(void* const* d_in, const int* in_sizes, int n_in,
                              void* d_out, int out_size) {
    const float* feats = (const float*)d_in[0];
    float* out = (float*)d_out;
    int n = in_sizes[0] / 64;   // WIDTH = 64 -> N = 400000
    int m = out_size;           // 1000

    fps_init_kernel<<<1, 32>>>();
    fps_pack_kernel<<<(n + 255) / 256, 256>>>(feats, n);

    void* args[4] = { (void*)&feats, (void*)&n, (void*)&m, (void*)&out };
    cudaLaunchCooperativeKernel((void*)fps_coop_kernel,
                                dim3(NBLK), dim3(NTHR), args, 0, (cudaStream_t)0);
}

// round 13
// speedup vs baseline: 15.7457x; 1.1523x over previous
#include <cuda_runtime.h>
#include <cuda_bf16.h>

// Furthest-point sampling — round 13: shorten the per-iteration critical path.
// Base: round-12's passing kernel (3888us; counter barrier proven). Changes:
//   1) winner COORDS ride every reduction stage (thread->warp->block->grid):
//      blocks publish {key u64, coords float4}; the post-detect reduce selects
//      coords with keys -> the dependent g_xyz[widx] L2 load is GONE (and so
//      is the pack kernel).
//   2) 256 threads/block, 11 points/thread: block reduce fan-in 8 warps
//      instead of 32 (extra point updates are ILP-hidden).
//   3) scoped release/acquire (red.release.gpu.add / ld.acquire.gpu) replace
//      full __threadfence MEMBARs around the barrier.
//
// Barrier (round-2/12-proven shape): lane0 publishes partials with __stcg,
// arrives with a release-red on the monotone counter; warp0 spins on an
// acquire-load until cnt >= 148*(i+1); partials parity double-buffered
// (read of buffer p at iter i completes before any block can publish into
// p at iter i+2, separated by iter i+1's full barrier).
//
// Output stored as FLOAT32 (validator reads d_out as f32 — round-9 root cause).
//
// Math (validated EXACT, rel_err = 0.0): __fadd_rn/__fmul_rn, left-to-right
// ((dx^2+dy^2)+dz^2), fminf; key = (float_bits(dist)<<32) | (0xFFFFFFFF-idx);
// dist >= 0 keeps float bits order-preserving; complemented idx makes max()
// prefer the SMALLEST index on exact ties (jnp.argmax first-occurrence);
// thread-local scan ascends in index with strict '>'.

#define NBLK  148
#define NTHR  256
#define NWARP (NTHR / 32)
#define PPT   11     // 148*256*11 = 416768 >= 400000

__device__ unsigned long long g_partK[2][NBLK];
__device__ float4 g_partC[2][NBLK];
__device__ unsigned int g_cnt;

__device__ __forceinline__ unsigned int ld_acquire_gpu_u32(const unsigned int* p) {
    unsigned int v;
    asm volatile("ld.acquire.gpu.global.u32 %0, [%1];" : "=r"(v) : "l"(p) : "memory");
    return v;
}
__device__ __forceinline__ void red_release_gpu_add_u32(unsigned int* p, unsigned int v) {
    asm volatile("red.release.gpu.global.add.u32 [%0], %1;" :: "l"(p), "r"(v) : "memory");
}

__global__ void fps_init_kernel() {
    if (threadIdx.x == 0) g_cnt = 0u;
}

__global__ __launch_bounds__(NTHR, 1)
void fps_coop_kernel(const float* __restrict__ feats, int n, int m,
                     float* __restrict__ out)
{
    const int tid  = threadIdx.x;
    const int bid  = blockIdx.x;
    const int gtid = bid * NTHR + tid;
    const int lane = tid & 31;
    const int warp = tid >> 5;
    const int stride = NBLK * NTHR;

    // Register-resident point state (11 points/thread)
    float px[PPT], py[PPT], pz[PPT], dist[PPT];
#pragma unroll
    for (int k = 0; k < PPT; ++k) {
        int g = gtid + k * stride;
        if (g < n) {
            // feats row = 64 floats (256B); first 16B aligned -> one LDG.128
            float4 v = *reinterpret_cast<const float4*>(feats + (size_t)g * 64);
            px[k] = v.x; py[k] = v.y; pz[k] = v.z;
        } else {
            px[k] = 0.f; py[k] = 0.f; pz[k] = 0.f;
        }
        dist[k] = 1e10f;
    }

    float qx = feats[0], qy = feats[1], qz = feats[2];   // seed = index 0
    if (gtid == 0) out[0] = 0.0f;

    __shared__ unsigned long long s_redK[NWARP];
    __shared__ float4 s_redC[NWARP];
    __shared__ float s_q[3];
    __shared__ unsigned int s_widx;

    for (int i = 0; i < m - 1; ++i) {
        // ---- 1) min-dist update + thread-local argmax (coords tracked) ----
        float bestd = -1.0f, bx = 0.f, by = 0.f, bz = 0.f;
        int   besti = 0;
#pragma unroll
        for (int k = 0; k < PPT; ++k) {
            int g = gtid + k * stride;
            float dx = __fadd_rn(px[k], -qx);
            float dy = __fadd_rn(py[k], -qy);
            float dz = __fadd_rn(pz[k], -qz);
            float d  = __fadd_rn(__fadd_rn(__fmul_rn(dx, dx),
                                           __fmul_rn(dy, dy)),
                                 __fmul_rn(dz, dz));
            float nd = fminf(dist[k], d);
            dist[k] = nd;
            if (g < n && nd > bestd) {       // ascending g: first-max kept
                bestd = nd; besti = g;
                bx = px[k]; by = py[k]; bz = pz[k];
            }
        }
        unsigned long long key =
            ((unsigned long long)__float_as_uint(bestd) << 32) |
            (unsigned long long)(0xFFFFFFFFu - (unsigned)besti);

        // ---- 2) warp tuple argmax (key + coords) ----
#pragma unroll
        for (int off = 16; off > 0; off >>= 1) {
            unsigned long long ok = __shfl_down_sync(0xFFFFFFFFu, key, off);
            float ox = __shfl_down_sync(0xFFFFFFFFu, bx, off);
            float oy = __shfl_down_sync(0xFFFFFFFFu, by, off);
            float oz = __shfl_down_sync(0xFFFFFFFFu, bz, off);
            if (ok > key) { key = ok; bx = ox; by = oy; bz = oz; }
        }
        if (lane == 0) {
            s_redK[warp] = key;
            s_redC[warp] = make_float4(bx, by, bz, 0.f);
        }
        __syncthreads();

        if (warp == 0) {
            // ---- 3) block tuple argmax over 8 warps ----
            key = (lane < NWARP) ? s_redK[lane] : 0ull;
            float4 c = (lane < NWARP) ? s_redC[lane]
                                      : make_float4(0.f, 0.f, 0.f, 0.f);
#pragma unroll
            for (int off = 4; off > 0; off >>= 1) {
                unsigned long long ok = __shfl_down_sync(0xFFFFFFFFu, key, off);
                float ox = __shfl_down_sync(0xFFFFFFFFu, c.x, off);
                float oy = __shfl_down_sync(0xFFFFFFFFu, c.y, off);
                float oz = __shfl_down_sync(0xFFFFFFFFu, c.z, off);
                if (ok > key) { key = ok; c.x = ox; c.y = oy; c.z = oz; }
            }

            // ---- 4) publish {key, coords}; release-arrive on counter ----
            if (lane == 0) {
                __stcg(&g_partK[i & 1][bid], key);
                __stcg(&g_partC[i & 1][bid], c);
                red_release_gpu_add_u32(&g_cnt, 1u);   // orders prior stores
            }

            // ---- 5) spin until all 148 blocks arrived (acquire) ----
            const unsigned int target = (unsigned)(i + 1) * (unsigned)NBLK;
            while (ld_acquire_gpu_u32(&g_cnt) < target) { }

            // ---- 6) grid tuple argmax over the 148 partials ----
            unsigned long long bk = 0ull;
            float4 bc = make_float4(0.f, 0.f, 0.f, 0.f);
            for (int j = lane; j < NBLK; j += 32) {
                unsigned long long k2 = __ldcg(&g_partK[i & 1][j]);
                float4 c2 = __ldcg(&g_partC[i & 1][j]);
                if (k2 > bk) { bk = k2; bc = c2; }
            }
#pragma unroll
            for (int off = 16; off > 0; off >>= 1) {
                unsigned long long ok = __shfl_down_sync(0xFFFFFFFFu, bk, off);
                float ox = __shfl_down_sync(0xFFFFFFFFu, bc.x, off);
                float oy = __shfl_down_sync(0xFFFFFFFFu, bc.y, off);
                float oz = __shfl_down_sync(0xFFFFFFFFu, bc.z, off);
                if (ok > bk) { bk = ok; bc.x = ox; bc.y = oy; bc.z = oz; }
            }
            if (lane == 0) {
                s_q[0] = bc.x; s_q[1] = bc.y; s_q[2] = bc.z;
                s_widx = 0xFFFFFFFFu - (unsigned int)(bk & 0xFFFFFFFFull);
            }
        }
        __syncthreads();

        // ---- 7) broadcast winner; store index AS FLOAT ----
        qx = s_q[0]; qy = s_q[1]; qz = s_q[2];
        if (bid == 0 && tid == 0) out[i + 1] = (float)s_widx;
        // WAR safety: s_red*/s_q rewritten only after all threads pass this
        // iteration's two __syncthreads. Partials parity buffer p: read at
        // iter i precedes any block's publish into p at iter i+2, separated
        // by iter i+1's full arrival round.
    }
}

extern "C" void kernel_launch(void* const* d_in, const int* in_sizes, int n_in,
                              void* d_out, int out_size) {
    const float* feats = (const float*)d_in[0];
    float* out = (float*)d_out;
    int n = in_sizes[0] / 64;   // WIDTH = 64 -> N = 400000
    int m = out_size;           // 1000

    fps_init_kernel<<<1, 32>>>();

    void* args[4] = { (void*)&feats, (void*)&n, (void*)&m, (void*)&out };
    cudaLaunchCooperativeKernel((void*)fps_coop_kernel,
                                dim3(NBLK), dim3(NTHR), args, 0, (cudaStream_t)0);
}

// round 15
// speedup vs baseline: 19.1322x; 1.2151x over previous
#include <cuda_runtime.h>
#include <cuda_bf16.h>

// Furthest-point sampling — round 15: round-14 tagged-slot design, compile
// fix only (volatile uint4 assignment -> __stcg uint4 overload).
//
// Each block publishes its per-iteration partial argmax as ONE 16-byte
// STG.128 (.cg): {tag = i+1, key_hi, key_lo, 0}. The tag rides in the same
// L2 transaction as the data, so no release fence, no atomic counter, and
// no detect->then->read dependent round-trip: consumers poll the 64 slots
// directly with __ldcv until every tag equals i+1 (flag-rides-with-data).
//
// Serial chain removed vs round 13 (3374us): release-commit RTT + ATOMG +
// counter-poll RTT + dependent partial-read RTT  ->  slot-commit + poll-hit.
//
// Parity double-buffering makes tag reuse impossible: a block can publish
// iter i+2 into parity p only after its poll of iter i+1 (parity p^1)
// passes, which requires every block's publish(i+1), which follows their
// poll(i) reads of parity p. Tags strictly increase; init kernel re-zeros
// the slots on every graph replay.
//
// Grid: 64 blocks x 256 threads, 25 points/thread (64*256*25 = 409600 >=
// 400000). Poll fan-in = exactly 2 slots per lane of warp 0. Winner coords
// from the packed L2-hot g_xyz table (off the fan-in path).
//
// Output stored as FLOAT32 (round-9 root cause: validator reads d_out as f32).
//
// Math (validated EXACT, rel_err = 0.0 in rounds 9/10/12/13):
//   dists: __fadd_rn/__fmul_rn, left-to-right ((dx^2+dy^2)+dz^2), fminf.
//   key = (float_bits(dist)<<32) | (0xFFFFFFFF - idx); dist >= 0 keeps float
//   bits order-preserving; complemented idx => max() prefers the SMALLEST
//   index on exact ties (jnp.argmax first-occurrence); thread-local scan
//   ascends in index with strict '>'.

#define N_MAX 400000
#define NBLK  64
#define NTHR  256
#define NWARP (NTHR / 32)
#define PPT   25     // 64*256*25 = 409600 >= 400000

__device__ float4 g_xyz[N_MAX];          // packed coords (L2-hot, 6.4MB)
__device__ uint4  g_slot[2][NBLK];       // {tag, key_hi, key_lo, 0}

__global__ void fps_init_kernel() {
    int t = threadIdx.x;
    if (t < 2 * NBLK)
        ((uint4*)g_slot)[t] = make_uint4(0u, 0u, 0u, 0u);
}

__global__ void fps_pack_kernel(const float* __restrict__ feats, int n) {
    int g = blockIdx.x * blockDim.x + threadIdx.x;
    if (g < n) {
        float4 v = *reinterpret_cast<const float4*>(feats + (size_t)g * 64);
        g_xyz[g] = make_float4(v.x, v.y, v.z, 0.0f);
    }
}

__global__ __launch_bounds__(NTHR, 1)
void fps_coop_kernel(const float* __restrict__ feats, int n, int m,
                     float* __restrict__ out)
{
    const int tid  = threadIdx.x;
    const int bid  = blockIdx.x;
    const int gtid = bid * NTHR + tid;
    const int lane = tid & 31;
    const int warp = tid >> 5;
    const int stride = NBLK * NTHR;      // 16384

    // Register-resident point state (25 points/thread)
    float px[PPT], py[PPT], pz[PPT], dist[PPT];
#pragma unroll
    for (int k = 0; k < PPT; ++k) {
        int g = gtid + k * stride;
        if (g < n) {
            // feats row = 64 floats (256B); first 16B aligned -> one LDG.128
            float4 v = *reinterpret_cast<const float4*>(feats + (size_t)g * 64);
            px[k] = v.x; py[k] = v.y; pz[k] = v.z;
        } else {
            px[k] = 0.f; py[k] = 0.f; pz[k] = 0.f;
        }
        dist[k] = 1e10f;
    }

    float qx = feats[0], qy = feats[1], qz = feats[2];   // seed = index 0
    if (gtid == 0) out[0] = 0.0f;

    __shared__ unsigned long long s_red[NWARP];
    __shared__ float s_q[3];
    __shared__ unsigned int s_widx;

    for (int i = 0; i < m - 1; ++i) {
        // ---- 1) min-dist update + thread-local best (ascending: first max) ----
        float bestd = -1.0f;
        int   besti = 0;
#pragma unroll
        for (int k = 0; k < PPT; ++k) {
            int g = gtid + k * stride;
            float dx = __fadd_rn(px[k], -qx);
            float dy = __fadd_rn(py[k], -qy);
            float dz = __fadd_rn(pz[k], -qz);
            float d  = __fadd_rn(__fadd_rn(__fmul_rn(dx, dx),
                                           __fmul_rn(dy, dy)),
                                 __fmul_rn(dz, dz));
            float nd = fminf(dist[k], d);
            dist[k] = nd;
            if (g < n && nd > bestd) { bestd = nd; besti = g; }
        }
        unsigned long long key =
            ((unsigned long long)__float_as_uint(bestd) << 32) |
            (unsigned long long)(0xFFFFFFFFu - (unsigned)besti);

        // ---- 2) warp + block key argmax ----
#pragma unroll
        for (int off = 16; off > 0; off >>= 1) {
            unsigned long long o = __shfl_down_sync(0xFFFFFFFFu, key, off);
            key = (o > key) ? o : key;
        }
        if (lane == 0) s_red[warp] = key;
        __syncthreads();

        if (warp == 0) {
            key = (lane < NWARP) ? s_red[lane] : 0ull;
#pragma unroll
            for (int off = 4; off > 0; off >>= 1) {
                unsigned long long o = __shfl_down_sync(0xFFFFFFFFu, key, off);
                key = (o > key) ? o : key;
            }

            // ---- 3) publish tagged slot: ONE 16B .cg transaction ----
            if (lane == 0) {
                uint4 s = make_uint4((unsigned)(i + 1),
                                     (unsigned)(key >> 32),
                                     (unsigned)(key & 0xFFFFFFFFull), 0u);
                __stcg(&g_slot[i & 1][bid], s);
            }

            // ---- 4) poll all 64 slots (2 per lane), tag == i+1 ----
            const unsigned want = (unsigned)(i + 1);
            const int par = i & 1;
            unsigned long long k0 = 0ull, k1 = 0ull;
            bool d0 = false, d1 = false;
            for (;;) {
                if (!d0) {
                    uint4 t = __ldcv(&g_slot[par][lane]);
                    if (t.x == want) {
                        k0 = ((unsigned long long)t.y << 32) | t.z;
                        d0 = true;
                    }
                }
                if (!d1) {
                    uint4 t = __ldcv(&g_slot[par][lane + 32]);
                    if (t.x == want) {
                        k1 = ((unsigned long long)t.y << 32) | t.z;
                        d1 = true;
                    }
                }
                if (__all_sync(0xFFFFFFFFu, d0 && d1)) break;
            }

            // ---- 5) grid key argmax over the 64 partials ----
            unsigned long long bk = (k0 > k1) ? k0 : k1;
#pragma unroll
            for (int off = 16; off > 0; off >>= 1) {
                unsigned long long o = __shfl_down_sync(0xFFFFFFFFu, bk, off);
                bk = (o > bk) ? o : bk;
            }
            if (lane == 0) {
                unsigned int widx =
                    0xFFFFFFFFu - (unsigned int)(bk & 0xFFFFFFFFull);
                float4 q = g_xyz[widx];          // L2-hot packed coords
                s_q[0] = q.x; s_q[1] = q.y; s_q[2] = q.z;
                s_widx = widx;
            }
        }
        __syncthreads();

        // ---- 6) broadcast winner; store index AS FLOAT ----
        qx = s_q[0]; qy = s_q[1]; qz = s_q[2];
        if (bid == 0 && tid == 0) out[i + 1] = (float)s_widx;
        // WAR safety: s_red/s_q rewritten only after all threads pass this
        // iteration's two __syncthreads; slot parity analyzed in header.
    }
}

extern "C" void kernel_launch(void* const* d_in, const int* in_sizes, int n_in,
                              void* d_out, int out_size) {
    const float* feats = (const float*)d_in[0];
    float* out = (float*)d_out;
    int n = in_sizes[0] / 64;   // WIDTH = 64 -> N = 400000
    int m = out_size;           // 1000

    fps_init_kernel<<<1, 128>>>();
    fps_pack_kernel<<<(n + 255) / 256, 256>>>(feats, n);

    void* args[4] = { (void*)&feats, (void*)&n, (void*)&m, (void*)&out };
    cudaLaunchCooperativeKernel((void*)fps_coop_kernel,
                                dim3(NBLK), dim3(NTHR), args, 0, (cudaStream_t)0);
}